// round 9
// baseline (speedup 1.0000x reference)
#include <cuda_runtime.h>
#include <cuda_bf16.h>
#include <math.h>
#include <math_constants.h>
#include <cstdint>

#define CB 4
#define CN 1024
#define CD 1024
#define CH 8
#define CHD 128
#define CD4 4096

typedef __nv_bfloat16 bf16;

// ---------------------------------------------------------------------------
// Device-global scratch (fp32 dataflow, proven in R5)
// ---------------------------------------------------------------------------
__device__ __align__(1024) float g_normed[CB * CN * CD];              // 16 MB
__device__ __align__(1024) float g_normed2[CB * CN * CD];             // 16 MB
__device__ __align__(1024) float g_x1[CB * CN * CD];                  // 16 MB
__device__ __align__(1024) float g_scores[(size_t)32 * CN * CN];      // 128 MB
__device__ __align__(1024) float g_hbuf[(size_t)CB * CN * CD4];       // 64 MB

// ---------------------------------------------------------------------------
// Helpers
// ---------------------------------------------------------------------------
__device__ __forceinline__ void mma16816(float* d, const uint32_t* a,
                                         const uint32_t* b) {
    asm volatile(
        "mma.sync.aligned.m16n8k16.row.col.f32.bf16.bf16.f32 "
        "{%0,%1,%2,%3}, {%4,%5,%6,%7}, {%8,%9}, {%0,%1,%2,%3};"
        : "+f"(d[0]), "+f"(d[1]), "+f"(d[2]), "+f"(d[3])
        : "r"(a[0]), "r"(a[1]), "r"(a[2]), "r"(a[3]), "r"(b[0]), "r"(b[1]));
}

__device__ __forceinline__ void cp16(uint32_t dst, const void* src) {
    asm volatile("cp.async.cg.shared.global [%0], [%1], 16;"
                 :: "r"(dst), "l"(__cvta_generic_to_global(src)));
}
__device__ __forceinline__ void cp_commit() {
    asm volatile("cp.async.commit_group;" ::: "memory");
}
template <int N>
__device__ __forceinline__ void cp_wait() {
    asm volatile("cp.async.wait_group %0;" :: "n"(N) : "memory");
}
__device__ __forceinline__ uint32_t smem_u32(const void* p) {
    uint32_t a;
    asm("{ .reg .u64 t; cvta.to.shared.u64 t, %1; cvt.u32.u64 %0, t; }"
        : "=r"(a) : "l"(p));
    return a;
}

__device__ __forceinline__ uint32_t pack2(bf16 a, bf16 b) {
    __nv_bfloat162 p = __halves2bfloat162(a, b);
    return *reinterpret_cast<uint32_t*>(&p);
}
__device__ __forceinline__ void split4(float4 v, uint2& hi, uint2& lo) {
    bf16 h0 = __float2bfloat16_rn(v.x), h1 = __float2bfloat16_rn(v.y);
    bf16 h2 = __float2bfloat16_rn(v.z), h3 = __float2bfloat16_rn(v.w);
    hi.x = pack2(h0, h1);
    hi.y = pack2(h2, h3);
    lo.x = pack2(__float2bfloat16_rn(v.x - __bfloat162float(h0)),
                 __float2bfloat16_rn(v.y - __bfloat162float(h1)));
    lo.y = pack2(__float2bfloat16_rn(v.z - __bfloat162float(h2)),
                 __float2bfloat16_rn(v.w - __bfloat162float(h3)));
}
__device__ __forceinline__ void splitpack(float a, float b, uint32_t& hi,
                                          uint32_t& lo) {
    bf16 ha = __float2bfloat16_rn(a), hb = __float2bfloat16_rn(b);
    hi = pack2(ha, hb);
    lo = pack2(__float2bfloat16_rn(a - __bfloat162float(ha)),
               __float2bfloat16_rn(b - __bfloat162float(hb)));
}

// smem layout (single stage, sized for 2 CTAs/SM):
//   A: 18432B  (128 rows x 144B: [hi 64B][lo 64B][pad 16B])
//   B: 18432B  (OP0: split 144B rows; else fp32 [32 rows][132 floats])
static constexpr int AROW = 144;
static constexpr int ABYTES = 128 * AROW;           // 18432
static constexpr int BROWF = 132 * 4;               // 528 bytes
static constexpr int DYN_SMEM = 2 * ABYTES;         // 36864

// ---------------------------------------------------------------------------
// Unified 128x128-tile split-bf16 mma.sync GEMM; 2 CTAs/SM hide latency.
// OP 0: scores   A=normed  B=normed (n-major) -> g_scores (scale*gate, mask)
// OP 1: attnout  A=scores(P) B=normed [k][n]  -> g_x1 = x + O
// OP 2: mlp1     A=normed2 B=W1 [k][n]        -> g_hbuf = gelu(acc + b1)
// OP 3: mlp2     A=hbuf    B=W2 [k][n]        -> out = x1 + acc + b2
// ---------------------------------------------------------------------------
template <int OP>
__global__ void __launch_bounds__(256, 2)
gemm128(const float* __restrict__ xin, const float* __restrict__ bias,
        const float* __restrict__ stoich, const float* __restrict__ gW,
        const float* __restrict__ gb, const int* __restrict__ adj,
        const float* __restrict__ Wmat, float* __restrict__ outf) {
    extern __shared__ char smem[];
    uint32_t sb = smem_u32(smem);

    int t = threadIdx.x, wid = t >> 5, lane = t & 31;
    int mw = wid >> 2, nwp = wid & 3;   // 2 x 4 warp grid (64x32 warp tile)
    int lg = lane >> 2, lt = (lane & 3) * 4;

    int m0, n0, b = 0, h = 0, bh = 0, lda, ldb, K;
    const float *Af, *Bf;
    if (OP == 0) {
        bh = blockIdx.z; b = bh >> 3; h = bh & 7;
        m0 = blockIdx.y * 128; n0 = blockIdx.x * 128;
        lda = ldb = CD; K = CHD;
        Af = g_normed + ((size_t)b * CN + m0) * CD + h * CHD;
        Bf = g_normed + ((size_t)b * CN + n0) * CD + h * CHD;
    } else if (OP == 1) {
        bh = blockIdx.z; b = bh >> 3; h = bh & 7;
        m0 = blockIdx.y * 128; n0 = 0;
        lda = CN; ldb = CD; K = CN;
        Af = g_scores + ((size_t)bh * CN + m0) * CN;
        Bf = g_normed + (size_t)b * CN * CD + h * CHD;
    } else if (OP == 2) {
        m0 = blockIdx.y * 128; n0 = blockIdx.x * 128;
        lda = CD; ldb = CD4; K = CD;
        Af = g_normed2 + (size_t)m0 * CD;
        Bf = Wmat + n0;
    } else {
        m0 = blockIdx.y * 128; n0 = blockIdx.x * 128;
        lda = CD4; ldb = CD; K = CD4;
        Af = g_hbuf + (size_t)m0 * CD4;
        Bf = Wmat + n0;
    }
    constexpr bool BKN = (OP != 0);  // B stored [K rows][N cols] in gmem

    float acc[4][4][4];
#pragma unroll
    for (int i = 0; i < 4; i++)
#pragma unroll
        for (int j = 0; j < 4; j++)
#pragma unroll
            for (int r = 0; r < 4; r++) acc[i][j][r] = 0.f;

    const int C = K / 32;

    // A loader mapping: row = ar + 32j, float4-slot aq (8 x 16B = 128B = 32 k)
    int ar = t >> 3, aq = t & 7;
    // B cp.async mapping: row = br + 8i, 16B-slot bq
    int br = t >> 5, bq = t & 31;

    char* abuf = smem;
    char* bbuf = smem + ABYTES;

    for (int c = 0; c < C; c++) {
        int k0 = c * 32;
        // ---- load phase (other CTA computes meanwhile) ----
        if (BKN) {
#pragma unroll
            for (int i = 0; i < 4; i++) {
                int row = br + 8 * i;
                cp16(sb + ABYTES + row * BROWF + bq * 16,
                     Bf + (size_t)(k0 + row) * ldb + bq * 4);
            }
            cp_commit();
        }
#pragma unroll
        for (int j = 0; j < 4; j++) {
            float4 v = *(const float4*)(Af + (size_t)(ar + 32 * j) * lda + k0 + aq * 4);
            uint2 hi, lo;
            split4(v, hi, lo);
            char* p = abuf + (ar + 32 * j) * AROW + aq * 8;
            *(uint2*)p = hi;
            *(uint2*)(p + 64) = lo;
        }
        if (!BKN) {
#pragma unroll
            for (int j = 0; j < 4; j++) {
                float4 v = *(const float4*)(Bf + (size_t)(ar + 32 * j) * ldb + k0 + aq * 4);
                uint2 hi, lo;
                split4(v, hi, lo);
                char* p = bbuf + (ar + 32 * j) * AROW + aq * 8;
                *(uint2*)p = hi;
                *(uint2*)(p + 64) = lo;
            }
        } else {
            cp_wait<0>();
        }
        __syncthreads();

        // ---- compute phase ----
#pragma unroll
        for (int ks = 0; ks < 2; ks++) {
            uint32_t bhf[4][2], blf[4][2];
            if (!BKN) {
#pragma unroll
                for (int nf = 0; nf < 4; nf++) {
                    const char* nb =
                        bbuf + (nwp * 32 + nf * 8 + lg) * AROW + ks * 32 + lt;
                    bhf[nf][0] = *(const uint32_t*)(nb);
                    bhf[nf][1] = *(const uint32_t*)(nb + 16);
                    blf[nf][0] = *(const uint32_t*)(nb + 64);
                    blf[nf][1] = *(const uint32_t*)(nb + 80);
                }
            } else {
                const float* bw = (const float*)bbuf;
                int kb2 = ks * 16 + (lane & 3) * 2;
#pragma unroll
                for (int nf = 0; nf < 4; nf++) {
                    int n = nwp * 32 + nf * 8 + lg;
                    float v0 = bw[(kb2 + 0) * 132 + n];
                    float v1 = bw[(kb2 + 1) * 132 + n];
                    float v8 = bw[(kb2 + 8) * 132 + n];
                    float v9 = bw[(kb2 + 9) * 132 + n];
                    splitpack(v0, v1, bhf[nf][0], blf[nf][0]);
                    splitpack(v8, v9, bhf[nf][1], blf[nf][1]);
                }
            }
#pragma unroll
            for (int mf = 0; mf < 4; mf++) {
                const char* ma =
                    abuf + (mw * 64 + mf * 16 + lg) * AROW + ks * 32 + lt;
                uint32_t ah[4], al[4];
                ah[0] = *(const uint32_t*)(ma);
                ah[1] = *(const uint32_t*)(ma + 8 * AROW);
                ah[2] = *(const uint32_t*)(ma + 16);
                ah[3] = *(const uint32_t*)(ma + 8 * AROW + 16);
                al[0] = *(const uint32_t*)(ma + 64);
                al[1] = *(const uint32_t*)(ma + 8 * AROW + 64);
                al[2] = *(const uint32_t*)(ma + 80);
                al[3] = *(const uint32_t*)(ma + 8 * AROW + 80);
#pragma unroll
                for (int nf = 0; nf < 4; nf++) {
                    mma16816(acc[mf][nf], ah, bhf[nf]);
                    mma16816(acc[mf][nf], ah, blf[nf]);
                    mma16816(acc[mf][nf], al, bhf[nf]);
                }
            }
        }
        __syncthreads();
    }

    // ---- fused epilogue (c-frag: rows lg, lg+8; cols (lane&3)*2 + {0,1}) ----
    int c0 = (lane & 3) * 2;
#pragma unroll
    for (int mf = 0; mf < 4; mf++) {
#pragma unroll
        for (int half = 0; half < 2; half++) {
            int gm = m0 + mw * 64 + mf * 16 + lg + half * 8;
            if (OP == 0) {
                float sq = stoich[b * CN + gm];
                size_t srow = ((size_t)bh << 20) + (size_t)gm * CN;
                const int* arow = adj + (size_t)b * CN * CN + (size_t)gm * CN;
#pragma unroll
                for (int nf = 0; nf < 4; nf++) {
#pragma unroll
                    for (int e = 0; e < 2; e++) {
                        int gn = n0 + nwp * 32 + nf * 8 + c0 + e;
                        float v = acc[mf][nf][half * 2 + e];
                        float gate =
                            1.f / (1.f + __expf(-(sq * gW[gn] + gb[gn])));
                        g_scores[srow + gn] =
                            (arow[gn] > 0) ? v * 0.08838834764831845f * gate
                                           : -CUDART_INF_F;
                    }
                }
            } else if (OP == 1) {
                size_t base = ((size_t)b * CN + gm) * CD + h * CHD;
#pragma unroll
                for (int nf = 0; nf < 4; nf++) {
#pragma unroll
                    for (int e = 0; e < 2; e++) {
                        int gn = nwp * 32 + nf * 8 + c0 + e;
                        g_x1[base + gn] =
                            xin[base + gn] + acc[mf][nf][half * 2 + e];
                    }
                }
            } else if (OP == 2) {
                size_t base = (size_t)gm * CD4;
#pragma unroll
                for (int nf = 0; nf < 4; nf++) {
#pragma unroll
                    for (int e = 0; e < 2; e++) {
                        int gn = n0 + nwp * 32 + nf * 8 + c0 + e;
                        float u = acc[mf][nf][half * 2 + e] + bias[gn];
                        g_hbuf[base + gn] =
                            0.5f * u * (1.f + erff(u * 0.7071067811865475f));
                    }
                }
            } else {
                size_t base = (size_t)gm * CD;
#pragma unroll
                for (int nf = 0; nf < 4; nf++) {
#pragma unroll
                    for (int e = 0; e < 2; e++) {
                        int gn = n0 + nwp * 32 + nf * 8 + c0 + e;
                        outf[base + gn] = g_x1[base + gn] +
                                          acc[mf][nf][half * 2 + e] + bias[gn];
                    }
                }
            }
        }
    }
}

// ---------------------------------------------------------------------------
// LayerNorm: sel==0: x -> g_normed ; sel==1: g_x1 -> g_normed2
// ---------------------------------------------------------------------------
__global__ void ln_kernel(const float* __restrict__ xext,
                          const float* __restrict__ lng,
                          const float* __restrict__ lnb,
                          int sel) {
    int row = blockIdx.x;
    const float* src = (sel == 0 ? xext : g_x1) + (size_t)row * CD;
    float* dst = (sel == 0 ? g_normed : g_normed2) + (size_t)row * CD;
    int t = threadIdx.x;

    float v[4];
    float s = 0.f;
#pragma unroll
    for (int i = 0; i < 4; i++) { v[i] = src[t + 256 * i]; s += v[i]; }

    __shared__ float red[8];
#pragma unroll
    for (int o = 16; o; o >>= 1) s += __shfl_xor_sync(0xffffffffu, s, o);
    if ((t & 31) == 0) red[t >> 5] = s;
    __syncthreads();
    float mean = (red[0] + red[1] + red[2] + red[3] +
                  red[4] + red[5] + red[6] + red[7]) * (1.f / CD);
    __syncthreads();

    float s2 = 0.f;
#pragma unroll
    for (int i = 0; i < 4; i++) { float d = v[i] - mean; s2 += d * d; }
#pragma unroll
    for (int o = 16; o; o >>= 1) s2 += __shfl_xor_sync(0xffffffffu, s2, o);
    if ((t & 31) == 0) red[t >> 5] = s2;
    __syncthreads();
    float var = (red[0] + red[1] + red[2] + red[3] +
                 red[4] + red[5] + red[6] + red[7]) * (1.f / CD);
    float rstd = rsqrtf(var + 1e-5f);

#pragma unroll
    for (int i = 0; i < 4; i++) {
        int c = t + 256 * i;
        dst[c] = (v[i] - mean) * rstd * lng[c] + lnb[c];
    }
}

// ---------------------------------------------------------------------------
// Row softmax over g_scores in place. grid B*H*N, 256 thr.
// ---------------------------------------------------------------------------
__global__ void softmax_kernel() {
    float* p = g_scores + (size_t)blockIdx.x * CN;
    int t = threadIdx.x;
    float v[4];
    float m = -CUDART_INF_F;
#pragma unroll
    for (int i = 0; i < 4; i++) { v[i] = p[t + 256 * i]; m = fmaxf(m, v[i]); }

    __shared__ float red[8];
#pragma unroll
    for (int o = 16; o; o >>= 1) m = fmaxf(m, __shfl_xor_sync(0xffffffffu, m, o));
    if ((t & 31) == 0) red[t >> 5] = m;
    __syncthreads();
    m = fmaxf(fmaxf(fmaxf(red[0], red[1]), fmaxf(red[2], red[3])),
              fmaxf(fmaxf(red[4], red[5]), fmaxf(red[6], red[7])));
    __syncthreads();

    float s = 0.f;
#pragma unroll
    for (int i = 0; i < 4; i++) { v[i] = __expf(v[i] - m); s += v[i]; }
#pragma unroll
    for (int o = 16; o; o >>= 1) s += __shfl_xor_sync(0xffffffffu, s, o);
    if ((t & 31) == 0) red[t >> 5] = s;
    __syncthreads();
    float tot = red[0] + red[1] + red[2] + red[3] +
                red[4] + red[5] + red[6] + red[7];
    float inv = 1.f / tot;
#pragma unroll
    for (int i = 0; i < 4; i++) p[t + 256 * i] = v[i] * inv;
}

// ---------------------------------------------------------------------------
// kernel_launch
// ---------------------------------------------------------------------------
extern "C" void kernel_launch(void* const* d_in, const int* in_sizes, int n_in,
                              void* d_out, int out_size) {
    const float* x      = (const float*)d_in[0];
    const int*   adj    = (const int*)d_in[1];
    const float* stoich = (const float*)d_in[2];
    const float* ln1_g  = (const float*)d_in[3];
    const float* ln1_b  = (const float*)d_in[4];
    const float* ln2_g  = (const float*)d_in[5];
    const float* ln2_b  = (const float*)d_in[6];
    const float* W1     = (const float*)d_in[7];
    const float* b1     = (const float*)d_in[8];
    const float* W2     = (const float*)d_in[9];
    const float* b2     = (const float*)d_in[10];
    const float* gW     = (const float*)d_in[11];
    const float* gb     = (const float*)d_in[12];
    float* out = (float*)d_out;

    // LN1: x -> g_normed
    ln_kernel<<<CB * CN, 256>>>(x, ln1_g, ln1_b, 0);

    // scores = gate-masked (Q Q^T)/sqrt(HD) -> g_scores
    gemm128<0><<<dim3(8, 8, CB * CH), 256, DYN_SMEM>>>(
        nullptr, nullptr, stoich, gW, gb, adj, nullptr, nullptr);

    // softmax rows (in place)
    softmax_kernel<<<CB * CH * CN, 256>>>();

    // attention out + residual -> g_x1
    gemm128<1><<<dim3(1, 8, CB * CH), 256, DYN_SMEM>>>(
        x, nullptr, nullptr, nullptr, nullptr, nullptr, nullptr, nullptr);

    // LN2: g_x1 -> g_normed2
    ln_kernel<<<CB * CN, 256>>>(x, ln2_g, ln2_b, 1);

    // MLP1: gelu(normed2 @ W1 + b1) -> g_hbuf
    gemm128<2><<<dim3(32, 32), 256, DYN_SMEM>>>(
        nullptr, b1, nullptr, nullptr, nullptr, nullptr, W1, nullptr);

    // MLP2: out = x1 + hbuf @ W2 + b2
    gemm128<3><<<dim3(8, 32), 256, DYN_SMEM>>>(
        nullptr, b2, nullptr, nullptr, nullptr, nullptr, W2, out);
}

// round 10
// speedup vs baseline: 1.3694x; 1.3694x over previous
#include <cuda_runtime.h>
#include <cuda_bf16.h>
#include <math.h>
#include <math_constants.h>
#include <cstdint>

#define CB 4
#define CN 1024
#define CD 1024
#define CH 8
#define CHD 128
#define CD4 4096

typedef __nv_bfloat16 bf16;

// ---------------------------------------------------------------------------
// Device-global scratch (fp32 dataflow, proven in R5)
// ---------------------------------------------------------------------------
__device__ __align__(1024) float g_normed[CB * CN * CD];              // 16 MB
__device__ __align__(1024) float g_normed2[CB * CN * CD];             // 16 MB
__device__ __align__(1024) float g_x1[CB * CN * CD];                  // 16 MB
__device__ __align__(1024) float g_scores[(size_t)32 * CN * CN];      // 128 MB
__device__ __align__(1024) float g_hbuf[(size_t)CB * CN * CD4];       // 64 MB

// ---------------------------------------------------------------------------
// Helpers
// ---------------------------------------------------------------------------
__device__ __forceinline__ void mma16816(float* d, const uint32_t* a,
                                         const uint32_t* b) {
    asm volatile(
        "mma.sync.aligned.m16n8k16.row.col.f32.bf16.bf16.f32 "
        "{%0,%1,%2,%3}, {%4,%5,%6,%7}, {%8,%9}, {%0,%1,%2,%3};"
        : "+f"(d[0]), "+f"(d[1]), "+f"(d[2]), "+f"(d[3])
        : "r"(a[0]), "r"(a[1]), "r"(a[2]), "r"(a[3]), "r"(b[0]), "r"(b[1]));
}
#define LDSM4(r0, r1, r2, r3, addr)                                            \
    asm volatile("ldmatrix.sync.aligned.m8n8.x4.shared.b16 {%0,%1,%2,%3}, [%4];" \
                 : "=r"(r0), "=r"(r1), "=r"(r2), "=r"(r3) : "r"(addr))
#define LDSM4T(r0, r1, r2, r3, addr)                                           \
    asm volatile("ldmatrix.sync.aligned.m8n8.x4.trans.shared.b16 {%0,%1,%2,%3}, [%4];" \
                 : "=r"(r0), "=r"(r1), "=r"(r2), "=r"(r3) : "r"(addr))

__device__ __forceinline__ uint32_t smem_u32(const void* p) {
    uint32_t a;
    asm("{ .reg .u64 t; cvta.to.shared.u64 t, %1; cvt.u32.u64 %0, t; }"
        : "=r"(a) : "l"(p));
    return a;
}
__device__ __forceinline__ uint32_t pack2(bf16 a, bf16 b) {
    __nv_bfloat162 p = __halves2bfloat162(a, b);
    return *reinterpret_cast<uint32_t*>(&p);
}
__device__ __forceinline__ void split4(float4 v, uint2& hi, uint2& lo) {
    bf16 h0 = __float2bfloat16_rn(v.x), h1 = __float2bfloat16_rn(v.y);
    bf16 h2 = __float2bfloat16_rn(v.z), h3 = __float2bfloat16_rn(v.w);
    hi.x = pack2(h0, h1);
    hi.y = pack2(h2, h3);
    lo.x = pack2(__float2bfloat16_rn(v.x - __bfloat162float(h0)),
                 __float2bfloat16_rn(v.y - __bfloat162float(h1)));
    lo.y = pack2(__float2bfloat16_rn(v.z - __bfloat162float(h2)),
                 __float2bfloat16_rn(v.w - __bfloat162float(h3)));
}

// smem layout:
//   A: 128 rows x 144B ([hi 64B][lo 64B][pad 16B])          = 18432B
//   B (OP0):  same 144B pair layout (n-rows)                 = 18432B
//   B (BKN):  two bf16 planes [32 k-rows][272B stride]       = 2 x 8704B
static constexpr int AROW = 144;
static constexpr int ABYTES = 128 * AROW;    // 18432
static constexpr int BROW = 272;             // 128 bf16 (256B) + 16B pad
static constexpr int BPLANE = 32 * BROW;     // 8704
static constexpr int DYN_SMEM = 2 * ABYTES;  // 36864 (covers both variants)

// ---------------------------------------------------------------------------
// Unified 128x128-tile split-bf16 mma.sync GEMM, ldmatrix fragment loads.
// OP 0: scores   A=normed  B=normed (n-major) -> g_scores (scale*gate, mask)
// OP 1: attnout  A=scores(P) B=normed [k][n]  -> g_x1 = x + O
// OP 2: mlp1     A=normed2 B=W1 [k][n]        -> g_hbuf = gelu(acc + b1)
// OP 3: mlp2     A=hbuf    B=W2 [k][n]        -> out = x1 + acc + b2
// ---------------------------------------------------------------------------
template <int OP>
__global__ void __launch_bounds__(256)
gemm128(const float* __restrict__ xin, const float* __restrict__ bias,
        const float* __restrict__ stoich, const float* __restrict__ gW,
        const float* __restrict__ gb, const int* __restrict__ adj,
        const float* __restrict__ Wmat, float* __restrict__ outf) {
    extern __shared__ char smem[];
    uint32_t sb = smem_u32(smem);

    int t = threadIdx.x, wid = t >> 5, lane = t & 31;
    int mw = wid >> 2, nwp = wid & 3;   // 2 x 4 warp grid (64x32 warp tile)
    int lg = lane >> 2;

    int m0, n0, b = 0, h = 0, bh = 0, lda, ldb, K;
    const float *Af, *Bf;
    if (OP == 0) {
        bh = blockIdx.z; b = bh >> 3; h = bh & 7;
        m0 = blockIdx.y * 128; n0 = blockIdx.x * 128;
        lda = ldb = CD; K = CHD;
        Af = g_normed + ((size_t)b * CN + m0) * CD + h * CHD;
        Bf = g_normed + ((size_t)b * CN + n0) * CD + h * CHD;
    } else if (OP == 1) {
        bh = blockIdx.z; b = bh >> 3; h = bh & 7;
        m0 = blockIdx.y * 128; n0 = 0;
        lda = CN; ldb = CD; K = CN;
        Af = g_scores + ((size_t)bh * CN + m0) * CN;
        Bf = g_normed + (size_t)b * CN * CD + h * CHD;
    } else if (OP == 2) {
        m0 = blockIdx.y * 128; n0 = blockIdx.x * 128;
        lda = CD; ldb = CD4; K = CD;
        Af = g_normed2 + (size_t)m0 * CD;
        Bf = Wmat + n0;
    } else {
        m0 = blockIdx.y * 128; n0 = blockIdx.x * 128;
        lda = CD4; ldb = CD; K = CD4;
        Af = g_hbuf + (size_t)m0 * CD4;
        Bf = Wmat + n0;
    }
    constexpr bool BKN = (OP != 0);  // B stored [K rows][N cols] in gmem

    float acc[4][4][4];
#pragma unroll
    for (int i = 0; i < 4; i++)
#pragma unroll
        for (int j = 0; j < 4; j++)
#pragma unroll
            for (int r = 0; r < 4; r++) acc[i][j][r] = 0.f;

    const int C = K / 32;

    // loader mappings
    int ar = t >> 3, aq = t & 7;        // A: row ar+32j, 16B-slot aq
    int bkr = t >> 5, bkq = t & 31;     // BKN B: k-row bkr+8j, float4-slot bkq

    // ldmatrix per-lane addresses (row-pair tiles; conflict-free by stride mod)
    int lane7 = lane & 7, g1 = (lane >> 3) & 1, g2 = lane >> 4;
    // A frag tiles: t0 rows0-7@k0, t1 rows8-15@k0, t2 rows0-7@k8, t3 rows8-15@k8
    uint32_t a_base = sb + (uint32_t)(mw * 64 + g1 * 8 + lane7) * AROW + g2 * 16;
    // OP0 B tiles: t0 n0-7@k0, t1 n0-7@k8, t2 n8-15@k0, t3 n8-15@k8
    uint32_t b_base;
    if (!BKN)
        b_base = sb + ABYTES + (uint32_t)(nwp * 32 + g2 * 8 + lane7) * AROW + g1 * 16;
    else
        // trans tiles: t0 k0-7@nf0, t1 k8-15@nf0, t2 k0-7@nf1, t3 k8-15@nf1
        b_base = sb + ABYTES + (uint32_t)(g1 * 8 + lane7) * BROW +
                 (uint32_t)(nwp * 32 + g2 * 8) * 2;

    char* abuf = smem;
    char* bbuf = smem + ABYTES;

    float4 rA[4], rB[4];

#define LDG_A(k0)                                                              \
    do {                                                                       \
        _Pragma("unroll") for (int j = 0; j < 4; j++)                          \
            rA[j] = *(const float4*)(Af + (size_t)(ar + 32 * j) * lda + (k0) + aq * 4); \
    } while (0)
#define LDG_B(k0)                                                              \
    do {                                                                       \
        if (!BKN) {                                                            \
            _Pragma("unroll") for (int j = 0; j < 4; j++)                      \
                rB[j] = *(const float4*)(Bf + (size_t)(ar + 32 * j) * ldb + (k0) + aq * 4); \
        } else {                                                               \
            _Pragma("unroll") for (int j = 0; j < 4; j++)                      \
                rB[j] = *(const float4*)(Bf + (size_t)((k0) + bkr + 8 * j) * ldb + bkq * 4); \
        }                                                                      \
    } while (0)
#define STS_AB()                                                               \
    do {                                                                       \
        _Pragma("unroll") for (int j = 0; j < 4; j++) {                        \
            uint2 hi, lo;                                                      \
            split4(rA[j], hi, lo);                                             \
            char* p = abuf + (ar + 32 * j) * AROW + aq * 8;                    \
            *(uint2*)p = hi;                                                   \
            *(uint2*)(p + 64) = lo;                                            \
        }                                                                      \
        if (!BKN) {                                                            \
            _Pragma("unroll") for (int j = 0; j < 4; j++) {                    \
                uint2 hi, lo;                                                  \
                split4(rB[j], hi, lo);                                         \
                char* p = bbuf + (ar + 32 * j) * AROW + aq * 8;                \
                *(uint2*)p = hi;                                               \
                *(uint2*)(p + 64) = lo;                                        \
            }                                                                  \
        } else {                                                               \
            _Pragma("unroll") for (int j = 0; j < 4; j++) {                    \
                uint2 hi, lo;                                                  \
                split4(rB[j], hi, lo);                                         \
                char* p = bbuf + (bkr + 8 * j) * BROW + bkq * 8;               \
                *(uint2*)p = hi;                                               \
                *(uint2*)(p + BPLANE) = lo;                                    \
            }                                                                  \
        }                                                                      \
    } while (0)

    LDG_A(0);
    LDG_B(0);
    STS_AB();
    __syncthreads();

    for (int c = 0; c < C; c++) {
        if (c + 1 < C) {
            LDG_A((c + 1) * 32);
            LDG_B((c + 1) * 32);
        }

#pragma unroll
        for (int ks = 0; ks < 2; ks++) {
            uint32_t bhf[4][2], blf[4][2];
            if (!BKN) {
                uint32_t ba = b_base + ks * 32;
                LDSM4(bhf[0][0], bhf[0][1], bhf[1][0], bhf[1][1], ba);
                LDSM4(bhf[2][0], bhf[2][1], bhf[3][0], bhf[3][1], ba + 16 * AROW);
                LDSM4(blf[0][0], blf[0][1], blf[1][0], blf[1][1], ba + 64);
                LDSM4(blf[2][0], blf[2][1], blf[3][0], blf[3][1], ba + 16 * AROW + 64);
            } else {
                uint32_t ba = b_base + ks * 16 * BROW;
                LDSM4T(bhf[0][0], bhf[0][1], bhf[1][0], bhf[1][1], ba);
                LDSM4T(bhf[2][0], bhf[2][1], bhf[3][0], bhf[3][1], ba + 32);
                LDSM4T(blf[0][0], blf[0][1], blf[1][0], blf[1][1], ba + BPLANE);
                LDSM4T(blf[2][0], blf[2][1], blf[3][0], blf[3][1], ba + BPLANE + 32);
            }
#pragma unroll
            for (int mf = 0; mf < 4; mf++) {
                uint32_t aa = a_base + mf * 16 * AROW + ks * 32;
                uint32_t ah[4], al[4];
                LDSM4(ah[0], ah[1], ah[2], ah[3], aa);
                LDSM4(al[0], al[1], al[2], al[3], aa + 64);
#pragma unroll
                for (int nf = 0; nf < 4; nf++) {
                    mma16816(acc[mf][nf], ah, bhf[nf]);
                    mma16816(acc[mf][nf], ah, blf[nf]);
                    mma16816(acc[mf][nf], al, bhf[nf]);
                }
            }
        }
        __syncthreads();
        if (c + 1 < C) {
            STS_AB();
            __syncthreads();
        }
    }

    // ---- fused epilogue (c-frag: rows lg, lg+8; cols (lane&3)*2 + {0,1}) ----
    int c0 = (lane & 3) * 2;
#pragma unroll
    for (int mf = 0; mf < 4; mf++) {
#pragma unroll
        for (int half = 0; half < 2; half++) {
            int gm = m0 + mw * 64 + mf * 16 + lg + half * 8;
            if (OP == 0) {
                float sq = stoich[b * CN + gm];
                size_t srow = ((size_t)bh << 20) + (size_t)gm * CN;
                const int* arow = adj + (size_t)b * CN * CN + (size_t)gm * CN;
#pragma unroll
                for (int nf = 0; nf < 4; nf++) {
#pragma unroll
                    for (int e = 0; e < 2; e++) {
                        int gn = n0 + nwp * 32 + nf * 8 + c0 + e;
                        float v = acc[mf][nf][half * 2 + e];
                        float gate =
                            1.f / (1.f + __expf(-(sq * gW[gn] + gb[gn])));
                        g_scores[srow + gn] =
                            (arow[gn] > 0) ? v * 0.08838834764831845f * gate
                                           : -CUDART_INF_F;
                    }
                }
            } else if (OP == 1) {
                size_t base = ((size_t)b * CN + gm) * CD + h * CHD;
#pragma unroll
                for (int nf = 0; nf < 4; nf++) {
#pragma unroll
                    for (int e = 0; e < 2; e++) {
                        int gn = nwp * 32 + nf * 8 + c0 + e;
                        g_x1[base + gn] =
                            xin[base + gn] + acc[mf][nf][half * 2 + e];
                    }
                }
            } else if (OP == 2) {
                size_t base = (size_t)gm * CD4;
#pragma unroll
                for (int nf = 0; nf < 4; nf++) {
#pragma unroll
                    for (int e = 0; e < 2; e++) {
                        int gn = n0 + nwp * 32 + nf * 8 + c0 + e;
                        float u = acc[mf][nf][half * 2 + e] + bias[gn];
                        g_hbuf[base + gn] =
                            0.5f * u * (1.f + erff(u * 0.7071067811865475f));
                    }
                }
            } else {
                size_t base = (size_t)gm * CD;
#pragma unroll
                for (int nf = 0; nf < 4; nf++) {
#pragma unroll
                    for (int e = 0; e < 2; e++) {
                        int gn = n0 + nwp * 32 + nf * 8 + c0 + e;
                        outf[base + gn] = g_x1[base + gn] +
                                          acc[mf][nf][half * 2 + e] + bias[gn];
                    }
                }
            }
        }
    }
#undef LDG_A
#undef LDG_B
#undef STS_AB
}

// ---------------------------------------------------------------------------
// LayerNorm: sel==0: x -> g_normed ; sel==1: g_x1 -> g_normed2
// ---------------------------------------------------------------------------
__global__ void ln_kernel(const float* __restrict__ xext,
                          const float* __restrict__ lng,
                          const float* __restrict__ lnb,
                          int sel) {
    int row = blockIdx.x;
    const float* src = (sel == 0 ? xext : g_x1) + (size_t)row * CD;
    float* dst = (sel == 0 ? g_normed : g_normed2) + (size_t)row * CD;
    int t = threadIdx.x;

    float v[4];
    float s = 0.f;
#pragma unroll
    for (int i = 0; i < 4; i++) { v[i] = src[t + 256 * i]; s += v[i]; }

    __shared__ float red[8];
#pragma unroll
    for (int o = 16; o; o >>= 1) s += __shfl_xor_sync(0xffffffffu, s, o);
    if ((t & 31) == 0) red[t >> 5] = s;
    __syncthreads();
    float mean = (red[0] + red[1] + red[2] + red[3] +
                  red[4] + red[5] + red[6] + red[7]) * (1.f / CD);
    __syncthreads();

    float s2 = 0.f;
#pragma unroll
    for (int i = 0; i < 4; i++) { float d = v[i] - mean; s2 += d * d; }
#pragma unroll
    for (int o = 16; o; o >>= 1) s2 += __shfl_xor_sync(0xffffffffu, s2, o);
    if ((t & 31) == 0) red[t >> 5] = s2;
    __syncthreads();
    float var = (red[0] + red[1] + red[2] + red[3] +
                 red[4] + red[5] + red[6] + red[7]) * (1.f / CD);
    float rstd = rsqrtf(var + 1e-5f);

#pragma unroll
    for (int i = 0; i < 4; i++) {
        int c = t + 256 * i;
        dst[c] = (v[i] - mean) * rstd * lng[c] + lnb[c];
    }
}

// ---------------------------------------------------------------------------
// Row softmax over g_scores in place. grid B*H*N, 256 thr.
// ---------------------------------------------------------------------------
__global__ void softmax_kernel() {
    float* p = g_scores + (size_t)blockIdx.x * CN;
    int t = threadIdx.x;
    float v[4];
    float m = -CUDART_INF_F;
#pragma unroll
    for (int i = 0; i < 4; i++) { v[i] = p[t + 256 * i]; m = fmaxf(m, v[i]); }

    __shared__ float red[8];
#pragma unroll
    for (int o = 16; o; o >>= 1) m = fmaxf(m, __shfl_xor_sync(0xffffffffu, m, o));
    if ((t & 31) == 0) red[t >> 5] = m;
    __syncthreads();
    m = fmaxf(fmaxf(fmaxf(red[0], red[1]), fmaxf(red[2], red[3])),
              fmaxf(fmaxf(red[4], red[5]), fmaxf(red[6], red[7])));
    __syncthreads();

    float s = 0.f;
#pragma unroll
    for (int i = 0; i < 4; i++) { v[i] = __expf(v[i] - m); s += v[i]; }
#pragma unroll
    for (int o = 16; o; o >>= 1) s += __shfl_xor_sync(0xffffffffu, s, o);
    if ((t & 31) == 0) red[t >> 5] = s;
    __syncthreads();
    float tot = red[0] + red[1] + red[2] + red[3] +
                red[4] + red[5] + red[6] + red[7];
    float inv = 1.f / tot;
#pragma unroll
    for (int i = 0; i < 4; i++) p[t + 256 * i] = v[i] * inv;
}

// ---------------------------------------------------------------------------
// kernel_launch
// ---------------------------------------------------------------------------
extern "C" void kernel_launch(void* const* d_in, const int* in_sizes, int n_in,
                              void* d_out, int out_size) {
    const float* x      = (const float*)d_in[0];
    const int*   adj    = (const int*)d_in[1];
    const float* stoich = (const float*)d_in[2];
    const float* ln1_g  = (const float*)d_in[3];
    const float* ln1_b  = (const float*)d_in[4];
    const float* ln2_g  = (const float*)d_in[5];
    const float* ln2_b  = (const float*)d_in[6];
    const float* W1     = (const float*)d_in[7];
    const float* b1     = (const float*)d_in[8];
    const float* W2     = (const float*)d_in[9];
    const float* b2     = (const float*)d_in[10];
    const float* gW     = (const float*)d_in[11];
    const float* gb     = (const float*)d_in[12];
    float* out = (float*)d_out;

    // LN1: x -> g_normed
    ln_kernel<<<CB * CN, 256>>>(x, ln1_g, ln1_b, 0);

    // scores = gate-masked (Q Q^T)/sqrt(HD) -> g_scores
    gemm128<0><<<dim3(8, 8, CB * CH), 256, DYN_SMEM>>>(
        nullptr, nullptr, stoich, gW, gb, adj, nullptr, nullptr);

    // softmax rows (in place)
    softmax_kernel<<<CB * CH * CN, 256>>>();

    // attention out + residual -> g_x1
    gemm128<1><<<dim3(1, 8, CB * CH), 256, DYN_SMEM>>>(
        x, nullptr, nullptr, nullptr, nullptr, nullptr, nullptr, nullptr);

    // LN2: g_x1 -> g_normed2
    ln_kernel<<<CB * CN, 256>>>(x, ln2_g, ln2_b, 1);

    // MLP1: gelu(normed2 @ W1 + b1) -> g_hbuf
    gemm128<2><<<dim3(32, 32), 256, DYN_SMEM>>>(
        nullptr, b1, nullptr, nullptr, nullptr, nullptr, W1, nullptr);

    // MLP2: out = x1 + hbuf @ W2 + b2
    gemm128<3><<<dim3(8, 32), 256, DYN_SMEM>>>(
        nullptr, b2, nullptr, nullptr, nullptr, nullptr, W2, out);
}

// round 12
// speedup vs baseline: 1.7376x; 1.2689x over previous
#include <cuda_runtime.h>
#include <cuda_bf16.h>
#include <math.h>
#include <math_constants.h>
#include <cstdint>

#define CB 4
#define CN 1024
#define CD 1024
#define CH 8
#define CHD 128
#define CD4 4096
#define MAXN 96

typedef __nv_bfloat16 bf16;

// ---------------------------------------------------------------------------
// Device-global scratch
// ---------------------------------------------------------------------------
__device__ __align__(1024) float g_normed[CB * CN * CD];              // 16 MB
__device__ __align__(1024) float g_normed2[CB * CN * CD];             // 16 MB
__device__ __align__(1024) float g_x1[CB * CN * CD];                  // 16 MB
__device__ __align__(1024) float g_hbuf[(size_t)CB * CN * CD4];       // 64 MB
__device__ __align__(1024) int g_nbr[(size_t)CB * CN * MAXN];         // 1.5 MB
__device__ __align__(1024) int g_ncnt[CB * CN];

// ---------------------------------------------------------------------------
// Helpers
// ---------------------------------------------------------------------------
__device__ __forceinline__ void mma16816(float* d, const uint32_t* a,
                                         const uint32_t* b) {
    asm volatile(
        "mma.sync.aligned.m16n8k16.row.col.f32.bf16.bf16.f32 "
        "{%0,%1,%2,%3}, {%4,%5,%6,%7}, {%8,%9}, {%0,%1,%2,%3};"
        : "+f"(d[0]), "+f"(d[1]), "+f"(d[2]), "+f"(d[3])
        : "r"(a[0]), "r"(a[1]), "r"(a[2]), "r"(a[3]), "r"(b[0]), "r"(b[1]));
}
#define LDSM4(r0, r1, r2, r3, addr)                                            \
    asm volatile("ldmatrix.sync.aligned.m8n8.x4.shared.b16 {%0,%1,%2,%3}, [%4];" \
                 : "=r"(r0), "=r"(r1), "=r"(r2), "=r"(r3) : "r"(addr))
#define LDSM4T(r0, r1, r2, r3, addr)                                           \
    asm volatile("ldmatrix.sync.aligned.m8n8.x4.trans.shared.b16 {%0,%1,%2,%3}, [%4];" \
                 : "=r"(r0), "=r"(r1), "=r"(r2), "=r"(r3) : "r"(addr))

__device__ __forceinline__ uint32_t smem_u32(const void* p) {
    uint32_t a;
    asm("{ .reg .u64 t; cvta.to.shared.u64 t, %1; cvt.u32.u64 %0, t; }"
        : "=r"(a) : "l"(p));
    return a;
}
__device__ __forceinline__ uint32_t pack2(bf16 a, bf16 b) {
    __nv_bfloat162 p = __halves2bfloat162(a, b);
    return *reinterpret_cast<uint32_t*>(&p);
}
__device__ __forceinline__ void split4(float4 v, uint2& hi, uint2& lo) {
    bf16 h0 = __float2bfloat16_rn(v.x), h1 = __float2bfloat16_rn(v.y);
    bf16 h2 = __float2bfloat16_rn(v.z), h3 = __float2bfloat16_rn(v.w);
    hi.x = pack2(h0, h1);
    hi.y = pack2(h2, h3);
    lo.x = pack2(__float2bfloat16_rn(v.x - __bfloat162float(h0)),
                 __float2bfloat16_rn(v.y - __bfloat162float(h1)));
    lo.y = pack2(__float2bfloat16_rn(v.z - __bfloat162float(h2)),
                 __float2bfloat16_rn(v.w - __bfloat162float(h3)));
}

// smem layout (MLP GEMMs):
//   A: 128 rows x 144B ([hi 64B][lo 64B][pad 16B])          = 18432B
//   B: two bf16 planes [32 k-rows][272B stride]             = 2 x 8704B
static constexpr int AROW = 144;
static constexpr int ABYTES = 128 * AROW;    // 18432
static constexpr int BROW = 272;             // 128 bf16 (256B) + 16B pad
static constexpr int BPLANE = 32 * BROW;     // 8704
static constexpr int DYN_SMEM = 2 * ABYTES;  // 36864

// ---------------------------------------------------------------------------
// 128x128-tile split-bf16 mma.sync GEMM (BKN form), ldmatrix fragment loads.
// OP 2: mlp1  A=normed2 B=W1 [k][n] -> g_hbuf = gelu(acc + b1)
// OP 3: mlp2  A=hbuf    B=W2 [k][n] -> out = x1 + acc + b2
// ---------------------------------------------------------------------------
template <int OP>
__global__ void __launch_bounds__(256)
gemm128(const float* __restrict__ bias, const float* __restrict__ Wmat,
        float* __restrict__ outf) {
    extern __shared__ char smem[];
    uint32_t sb = smem_u32(smem);

    int t = threadIdx.x, wid = t >> 5, lane = t & 31;
    int mw = wid >> 2, nwp = wid & 3;   // 2 x 4 warp grid (64x32 warp tile)
    int lg = lane >> 2;

    int m0 = blockIdx.y * 128, n0 = blockIdx.x * 128;
    int lda, ldb, K;
    const float *Af, *Bf;
    if (OP == 2) {
        lda = CD; ldb = CD4; K = CD;
        Af = g_normed2 + (size_t)m0 * CD;
        Bf = Wmat + n0;
    } else {
        lda = CD4; ldb = CD; K = CD4;
        Af = g_hbuf + (size_t)m0 * CD4;
        Bf = Wmat + n0;
    }

    float acc[4][4][4];
#pragma unroll
    for (int i = 0; i < 4; i++)
#pragma unroll
        for (int j = 0; j < 4; j++)
#pragma unroll
            for (int r = 0; r < 4; r++) acc[i][j][r] = 0.f;

    const int C = K / 32;

    int ar = t >> 3, aq = t & 7;        // A: row ar+32j, 16B-slot aq
    int bkr = t >> 5, bkq = t & 31;     // B: k-row bkr+8j, float4-slot bkq

    int lane7 = lane & 7, g1 = (lane >> 3) & 1, g2 = lane >> 4;
    uint32_t a_base = sb + (uint32_t)(mw * 64 + g1 * 8 + lane7) * AROW + g2 * 16;
    uint32_t b_base = sb + ABYTES + (uint32_t)(g1 * 8 + lane7) * BROW +
                      (uint32_t)(nwp * 32 + g2 * 8) * 2;

    char* abuf = smem;
    char* bbuf = smem + ABYTES;

    float4 rA[4], rB[4];

#define LDG_A(k0)                                                              \
    do {                                                                       \
        _Pragma("unroll") for (int j = 0; j < 4; j++)                          \
            rA[j] = *(const float4*)(Af + (size_t)(ar + 32 * j) * lda + (k0) + aq * 4); \
    } while (0)
#define LDG_B(k0)                                                              \
    do {                                                                       \
        _Pragma("unroll") for (int j = 0; j < 4; j++)                          \
            rB[j] = *(const float4*)(Bf + (size_t)((k0) + bkr + 8 * j) * ldb + bkq * 4); \
    } while (0)
#define STS_AB()                                                               \
    do {                                                                       \
        _Pragma("unroll") for (int j = 0; j < 4; j++) {                        \
            uint2 hi, lo;                                                      \
            split4(rA[j], hi, lo);                                             \
            char* p = abuf + (ar + 32 * j) * AROW + aq * 8;                    \
            *(uint2*)p = hi;                                                   \
            *(uint2*)(p + 64) = lo;                                            \
        }                                                                      \
        _Pragma("unroll") for (int j = 0; j < 4; j++) {                        \
            uint2 hi, lo;                                                      \
            split4(rB[j], hi, lo);                                             \
            char* p = bbuf + (bkr + 8 * j) * BROW + bkq * 8;                   \
            *(uint2*)p = hi;                                                   \
            *(uint2*)(p + BPLANE) = lo;                                        \
        }                                                                      \
    } while (0)

    LDG_A(0);
    LDG_B(0);
    STS_AB();
    __syncthreads();

    for (int c = 0; c < C; c++) {
        if (c + 1 < C) {
            LDG_A((c + 1) * 32);
            LDG_B((c + 1) * 32);
        }

#pragma unroll
        for (int ks = 0; ks < 2; ks++) {
            uint32_t bhf[4][2], blf[4][2];
            uint32_t ba = b_base + ks * 16 * BROW;
            LDSM4T(bhf[0][0], bhf[0][1], bhf[1][0], bhf[1][1], ba);
            LDSM4T(bhf[2][0], bhf[2][1], bhf[3][0], bhf[3][1], ba + 32);
            LDSM4T(blf[0][0], blf[0][1], blf[1][0], blf[1][1], ba + BPLANE);
            LDSM4T(blf[2][0], blf[2][1], blf[3][0], blf[3][1], ba + BPLANE + 32);
#pragma unroll
            for (int mf = 0; mf < 4; mf++) {
                uint32_t aa = a_base + mf * 16 * AROW + ks * 32;
                uint32_t ah[4], al[4];
                LDSM4(ah[0], ah[1], ah[2], ah[3], aa);
                LDSM4(al[0], al[1], al[2], al[3], aa + 64);
#pragma unroll
                for (int nf = 0; nf < 4; nf++) {
                    mma16816(acc[mf][nf], ah, bhf[nf]);
                    mma16816(acc[mf][nf], ah, blf[nf]);
                    mma16816(acc[mf][nf], al, bhf[nf]);
                }
            }
        }
        __syncthreads();
        if (c + 1 < C) {
            STS_AB();
            __syncthreads();
        }
    }

    // ---- fused epilogue ----
    int c0 = (lane & 3) * 2;
#pragma unroll
    for (int mf = 0; mf < 4; mf++) {
#pragma unroll
        for (int half = 0; half < 2; half++) {
            int gm = m0 + mw * 64 + mf * 16 + lg + half * 8;
            if (OP == 2) {
                size_t base = (size_t)gm * CD4;
#pragma unroll
                for (int nf = 0; nf < 4; nf++) {
#pragma unroll
                    for (int e = 0; e < 2; e++) {
                        int gn = n0 + nwp * 32 + nf * 8 + c0 + e;
                        float u = acc[mf][nf][half * 2 + e] + bias[gn];
                        g_hbuf[base + gn] =
                            0.5f * u * (1.f + erff(u * 0.7071067811865475f));
                    }
                }
            } else {
                size_t base = (size_t)gm * CD;
#pragma unroll
                for (int nf = 0; nf < 4; nf++) {
#pragma unroll
                    for (int e = 0; e < 2; e++) {
                        int gn = n0 + nwp * 32 + nf * 8 + c0 + e;
                        outf[base + gn] = g_x1[base + gn] +
                                          acc[mf][nf][half * 2 + e] + bias[gn];
                    }
                }
            }
        }
    }
#undef LDG_A
#undef LDG_B
#undef STS_AB
}

// ---------------------------------------------------------------------------
// Neighbor-list build: one block per (b,q) row; ordered compaction of adj>0.
// ---------------------------------------------------------------------------
__global__ void __launch_bounds__(256) nbr_build(const int* __restrict__ adj) {
    int bq = blockIdx.x;
    const int* row = adj + (size_t)bq * CN;
    int t = threadIdx.x, lane = t & 31, wid = t >> 5;
    int base = t * 4;
    int pr[4], c = 0;
#pragma unroll
    for (int i = 0; i < 4; i++) { pr[i] = (row[base + i] > 0); c += pr[i]; }
    // warp inclusive scan of c
    int sc = c;
#pragma unroll
    for (int o = 1; o < 32; o <<= 1) {
        int v = __shfl_up_sync(0xffffffffu, sc, o);
        if (lane >= o) sc += v;
    }
    __shared__ int wsum[8];
    if (lane == 31) wsum[wid] = sc;
    __syncthreads();
    int woff = 0;
    for (int w = 0; w < wid; w++) woff += wsum[w];
    int off = woff + sc - c;  // exclusive offset
    int* dst = g_nbr + (size_t)bq * MAXN;
#pragma unroll
    for (int i = 0; i < 4; i++) {
        if (pr[i]) {
            if (off < MAXN) dst[off] = base + i;
            off++;
        }
    }
    if (t == 255) g_ncnt[bq] = min(off, MAXN);
}

// ---------------------------------------------------------------------------
// Fused sparse attention with online softmax. One block per (b,q).
// out[b,q,:] = x[b,q,:] + sum_k softmax_k( scale*gate* <q_h, k_h> ) * v_k
// over neighbors only (masked entries are exactly 0 in softmax).
// ---------------------------------------------------------------------------
__global__ void __launch_bounds__(256) sparse_attn(
    const float* __restrict__ xin, const float* __restrict__ stoich,
    const float* __restrict__ gW, const float* __restrict__ gb) {
    int bq = blockIdx.x;
    int b = bq >> 10, q = bq & 1023;
    int t = threadIdx.x, wid = t >> 5, lane = t & 31;

    __shared__ float qrow[CD];
    __shared__ float krow[CD];
    __shared__ float sh_corr[8], sh_p[8], sh_l[8];
    __shared__ int nbr[MAXN];

    const float* nr = g_normed + (size_t)b * CN * CD;
    for (int i = t; i < CD; i += 256) qrow[i] = nr[(size_t)q * CD + i];
    int cnt = g_ncnt[bq];
    for (int i = t; i < cnt; i += 256) nbr[i] = g_nbr[(size_t)bq * MAXN + i];
    __syncthreads();

    float sq = stoich[b * CN + q];
    // per-warp (= per-head) online softmax state; uniform across the warp
    float m = -CUDART_INF_F, l = 0.f;
    float acc[4] = {0.f, 0.f, 0.f, 0.f};  // dims t, t+256, t+512, t+768

    for (int j = 0; j < cnt; j++) {
        int k = nbr[j];
        __syncthreads();  // everyone done reading krow from prev iter
        for (int i = t; i < CD; i += 256) krow[i] = nr[(size_t)k * CD + i];
        __syncthreads();

        // warp `wid` computes head `wid` dot product
        float d = 0.f;
#pragma unroll
        for (int i = 0; i < 4; i++) {
            int idx = wid * CHD + lane + 32 * i;
            d += qrow[idx] * krow[idx];
        }
#pragma unroll
        for (int o = 16; o; o >>= 1) d += __shfl_xor_sync(0xffffffffu, d, o);

        float gate = 1.f / (1.f + __expf(-(sq * gW[k] + gb[k])));
        float s = d * 0.08838834764831845f * gate;

        float mnew = fmaxf(m, s);
        float corr = __expf(m - mnew);  // first iter: exp(-inf) = 0
        float p = __expf(s - mnew);
        l = l * corr + p;
        m = mnew;
        if (lane == 0) { sh_corr[wid] = corr; sh_p[wid] = p; }
        __syncthreads();

#pragma unroll
        for (int i = 0; i < 4; i++) {
            int dpos = t + 256 * i;
            int h = dpos >> 7;
            acc[i] = acc[i] * sh_corr[h] + sh_p[h] * krow[dpos];
        }
    }

    if (lane == 0) sh_l[wid] = l;
    __syncthreads();
#pragma unroll
    for (int i = 0; i < 4; i++) {
        int dpos = t + 256 * i;
        int h = dpos >> 7;
        size_t idx = ((size_t)b * CN + q) * CD + dpos;
        g_x1[idx] = xin[idx] + acc[i] / sh_l[h];
    }
}

// ---------------------------------------------------------------------------
// LayerNorm: sel==0: x -> g_normed ; sel==1: g_x1 -> g_normed2
// ---------------------------------------------------------------------------
__global__ void ln_kernel(const float* __restrict__ xext,
                          const float* __restrict__ lng,
                          const float* __restrict__ lnb,
                          int sel) {
    int row = blockIdx.x;
    const float* src = (sel == 0 ? xext : g_x1) + (size_t)row * CD;
    float* dst = (sel == 0 ? g_normed : g_normed2) + (size_t)row * CD;
    int t = threadIdx.x;

    float v[4];
    float s = 0.f;
#pragma unroll
    for (int i = 0; i < 4; i++) { v[i] = src[t + 256 * i]; s += v[i]; }

    __shared__ float red[8];
#pragma unroll
    for (int o = 16; o; o >>= 1) s += __shfl_xor_sync(0xffffffffu, s, o);
    if ((t & 31) == 0) red[t >> 5] = s;
    __syncthreads();
    float mean = (red[0] + red[1] + red[2] + red[3] +
                  red[4] + red[5] + red[6] + red[7]) * (1.f / CD);
    __syncthreads();

    float s2 = 0.f;
#pragma unroll
    for (int i = 0; i < 4; i++) { float d = v[i] - mean; s2 += d * d; }
#pragma unroll
    for (int o = 16; o; o >>= 1) s2 += __shfl_xor_sync(0xffffffffu, s2, o);
    if ((t & 31) == 0) red[t >> 5] = s2;
    __syncthreads();
    float var = (red[0] + red[1] + red[2] + red[3] +
                 red[4] + red[5] + red[6] + red[7]) * (1.f / CD);
    float rstd = rsqrtf(var + 1e-5f);

#pragma unroll
    for (int i = 0; i < 4; i++) {
        int c = t + 256 * i;
        dst[c] = (v[i] - mean) * rstd * lng[c] + lnb[c];
    }
}

// ---------------------------------------------------------------------------
// kernel_launch
// ---------------------------------------------------------------------------
extern "C" void kernel_launch(void* const* d_in, const int* in_sizes, int n_in,
                              void* d_out, int out_size) {
    const float* x      = (const float*)d_in[0];
    const int*   adj    = (const int*)d_in[1];
    const float* stoich = (const float*)d_in[2];
    const float* ln1_g  = (const float*)d_in[3];
    const float* ln1_b  = (const float*)d_in[4];
    const float* ln2_g  = (const float*)d_in[5];
    const float* ln2_b  = (const float*)d_in[6];
    const float* W1     = (const float*)d_in[7];
    const float* b1     = (const float*)d_in[8];
    const float* W2     = (const float*)d_in[9];
    const float* b2     = (const float*)d_in[10];
    const float* gW     = (const float*)d_in[11];
    const float* gb     = (const float*)d_in[12];
    float* out = (float*)d_out;

    // LN1: x -> g_normed
    ln_kernel<<<CB * CN, 256>>>(x, ln1_g, ln1_b, 0);

    // neighbor lists from adjacency
    nbr_build<<<CB * CN, 256>>>(adj);

    // fused sparse attention (scores+gate+mask+softmax+PV+residual) -> g_x1
    sparse_attn<<<CB * CN, 256>>>(x, stoich, gW, gb);

    // LN2: g_x1 -> g_normed2
    ln_kernel<<<CB * CN, 256>>>(x, ln2_g, ln2_b, 1);

    // MLP1: gelu(normed2 @ W1 + b1) -> g_hbuf
    gemm128<2><<<dim3(32, 32), 256, DYN_SMEM>>>(b1, W1, nullptr);

    // MLP2: out = x1 + hbuf @ W2 + b2
    gemm128<3><<<dim3(8, 32), 256, DYN_SMEM>>>(b2, W2, out);
}

// round 17
// speedup vs baseline: 1.8158x; 1.0450x over previous
#include <cuda_runtime.h>
#include <cuda_bf16.h>
#include <math.h>
#include <math_constants.h>
#include <cstdint>

#define CB 4
#define CN 1024
#define CD 1024
#define CH 8
#define CHD 128
#define CD4 4096
#define MAXN 96

typedef __nv_bfloat16 bf16;

// ---------------------------------------------------------------------------
// Device-global scratch
// ---------------------------------------------------------------------------
__device__ __align__(1024) float g_normed[CB * CN * CD];              // 16 MB
__device__ __align__(1024) float g_normed2[CB * CN * CD];             // 16 MB
__device__ __align__(1024) float g_x1[CB * CN * CD];                  // 16 MB
__device__ __align__(1024) float g_hbuf[(size_t)CB * CN * CD4];       // 64 MB
__device__ __align__(1024) int g_nbr[(size_t)CB * CN * MAXN];         // 1.5 MB
__device__ __align__(1024) int g_ncnt[CB * CN];

// ---------------------------------------------------------------------------
// Helpers
// ---------------------------------------------------------------------------
__device__ __forceinline__ void mma16816(float* d, const uint32_t* a,
                                         const uint32_t* b) {
    asm volatile(
        "mma.sync.aligned.m16n8k16.row.col.f32.bf16.bf16.f32 "
        "{%0,%1,%2,%3}, {%4,%5,%6,%7}, {%8,%9}, {%0,%1,%2,%3};"
        : "+f"(d[0]), "+f"(d[1]), "+f"(d[2]), "+f"(d[3])
        : "r"(a[0]), "r"(a[1]), "r"(a[2]), "r"(a[3]), "r"(b[0]), "r"(b[1]));
}
#define LDSM4(r0, r1, r2, r3, addr)                                            \
    asm volatile("ldmatrix.sync.aligned.m8n8.x4.shared.b16 {%0,%1,%2,%3}, [%4];" \
                 : "=r"(r0), "=r"(r1), "=r"(r2), "=r"(r3) : "r"(addr))
#define LDSM4T(r0, r1, r2, r3, addr)                                           \
    asm volatile("ldmatrix.sync.aligned.m8n8.x4.trans.shared.b16 {%0,%1,%2,%3}, [%4];" \
                 : "=r"(r0), "=r"(r1), "=r"(r2), "=r"(r3) : "r"(addr))

__device__ __forceinline__ uint32_t smem_u32(const void* p) {
    uint32_t a;
    asm("{ .reg .u64 t; cvta.to.shared.u64 t, %1; cvt.u32.u64 %0, t; }"
        : "=r"(a) : "l"(p));
    return a;
}
__device__ __forceinline__ uint32_t pack2(bf16 a, bf16 b) {
    __nv_bfloat162 p = __halves2bfloat162(a, b);
    return *reinterpret_cast<uint32_t*>(&p);
}
__device__ __forceinline__ void split4(float4 v, uint2& hi, uint2& lo) {
    bf16 h0 = __float2bfloat16_rn(v.x), h1 = __float2bfloat16_rn(v.y);
    bf16 h2 = __float2bfloat16_rn(v.z), h3 = __float2bfloat16_rn(v.w);
    hi.x = pack2(h0, h1);
    hi.y = pack2(h2, h3);
    lo.x = pack2(__float2bfloat16_rn(v.x - __bfloat162float(h0)),
                 __float2bfloat16_rn(v.y - __bfloat162float(h1)));
    lo.y = pack2(__float2bfloat16_rn(v.z - __bfloat162float(h2)),
                 __float2bfloat16_rn(v.w - __bfloat162float(h3)));
}

// smem layout (MLP GEMMs):
//   A: 128 rows x 144B ([hi 64B][lo 64B][pad 16B])          = 18432B
//   B: two bf16 planes [32 k-rows][272B stride]             = 2 x 8704B
static constexpr int AROW = 144;
static constexpr int ABYTES = 128 * AROW;    // 18432
static constexpr int BROW = 272;             // 128 bf16 (256B) + 16B pad
static constexpr int BPLANE = 32 * BROW;     // 8704
static constexpr int DYN_SMEM = 2 * ABYTES;  // 36864

// ---------------------------------------------------------------------------
// 128x128-tile split-bf16 mma.sync GEMM (BKN form), ldmatrix fragment loads.
// Term-major MMA issue: 16 independent accumulators between reuses, so the
// asm-volatile MMA stream pipelines instead of chaining on acc.
// OP 2: mlp1  A=normed2 B=W1 [k][n] -> g_hbuf = gelu(acc + b1)
// OP 3: mlp2  A=hbuf    B=W2 [k][n] -> out = x1 + acc + b2
// ---------------------------------------------------------------------------
template <int OP>
__global__ void __launch_bounds__(256)
gemm128(const float* __restrict__ bias, const float* __restrict__ Wmat,
        float* __restrict__ outf) {
    extern __shared__ char smem[];
    uint32_t sb = smem_u32(smem);

    int t = threadIdx.x, wid = t >> 5, lane = t & 31;
    int mw = wid >> 2, nwp = wid & 3;   // 2 x 4 warp grid (64x32 warp tile)
    int lg = lane >> 2;

    int m0 = blockIdx.y * 128, n0 = blockIdx.x * 128;
    int lda, ldb, K;
    const float *Af, *Bf;
    if (OP == 2) {
        lda = CD; ldb = CD4; K = CD;
        Af = g_normed2 + (size_t)m0 * CD;
        Bf = Wmat + n0;
    } else {
        lda = CD4; ldb = CD; K = CD4;
        Af = g_hbuf + (size_t)m0 * CD4;
        Bf = Wmat + n0;
    }

    float acc[4][4][4];
#pragma unroll
    for (int i = 0; i < 4; i++)
#pragma unroll
        for (int j = 0; j < 4; j++)
#pragma unroll
            for (int r = 0; r < 4; r++) acc[i][j][r] = 0.f;

    const int C = K / 32;

    int ar = t >> 3, aq = t & 7;        // A: row ar+32j, 16B-slot aq
    int bkr = t >> 5, bkq = t & 31;     // B: k-row bkr+8j, float4-slot bkq

    int lane7 = lane & 7, g1 = (lane >> 3) & 1, g2 = lane >> 4;
    uint32_t a_base = sb + (uint32_t)(mw * 64 + g1 * 8 + lane7) * AROW + g2 * 16;
    uint32_t b_base = sb + ABYTES + (uint32_t)(g1 * 8 + lane7) * BROW +
                      (uint32_t)(nwp * 32 + g2 * 8) * 2;

    char* abuf = smem;
    char* bbuf = smem + ABYTES;

    float4 rA[4], rB[4];

#define LDG_A(k0)                                                              \
    do {                                                                       \
        _Pragma("unroll") for (int j = 0; j < 4; j++)                          \
            rA[j] = *(const float4*)(Af + (size_t)(ar + 32 * j) * lda + (k0) + aq * 4); \
    } while (0)
#define LDG_B(k0)                                                              \
    do {                                                                       \
        _Pragma("unroll") for (int j = 0; j < 4; j++)                          \
            rB[j] = *(const float4*)(Bf + (size_t)((k0) + bkr + 8 * j) * ldb + bkq * 4); \
    } while (0)
#define STS_AB()                                                               \
    do {                                                                       \
        _Pragma("unroll") for (int j = 0; j < 4; j++) {                        \
            uint2 hi, lo;                                                      \
            split4(rA[j], hi, lo);                                             \
            char* p = abuf + (ar + 32 * j) * AROW + aq * 8;                    \
            *(uint2*)p = hi;                                                   \
            *(uint2*)(p + 64) = lo;                                            \
        }                                                                      \
        _Pragma("unroll") for (int j = 0; j < 4; j++) {                        \
            uint2 hi, lo;                                                      \
            split4(rB[j], hi, lo);                                             \
            char* p = bbuf + (bkr + 8 * j) * BROW + bkq * 8;                   \
            *(uint2*)p = hi;                                                   \
            *(uint2*)(p + BPLANE) = lo;                                        \
        }                                                                      \
    } while (0)

    LDG_A(0);
    LDG_B(0);
    STS_AB();
    __syncthreads();

    for (int c = 0; c < C; c++) {
        if (c + 1 < C) {
            LDG_A((c + 1) * 32);
            LDG_B((c + 1) * 32);
        }

#pragma unroll
        for (int ks = 0; ks < 2; ks++) {
            uint32_t bhf[4][2], blf[4][2];
            uint32_t ba = b_base + ks * 16 * BROW;
            LDSM4T(bhf[0][0], bhf[0][1], bhf[1][0], bhf[1][1], ba);
            LDSM4T(bhf[2][0], bhf[2][1], bhf[3][0], bhf[3][1], ba + 32);
            LDSM4T(blf[0][0], blf[0][1], blf[1][0], blf[1][1], ba + BPLANE);
            LDSM4T(blf[2][0], blf[2][1], blf[3][0], blf[3][1], ba + BPLANE + 32);

            // load all A fragments for this k16 (4 mf tiles, hi+lo)
            uint32_t ah[4][4], al[4][4];
#pragma unroll
            for (int mf = 0; mf < 4; mf++) {
                uint32_t aa = a_base + mf * 16 * AROW + ks * 32;
                LDSM4(ah[mf][0], ah[mf][1], ah[mf][2], ah[mf][3], aa);
                LDSM4(al[mf][0], al[mf][1], al[mf][2], al[mf][3], aa + 64);
            }

            // term-major issue: per-acc order stays (hh, hl, lh) but the
            // distance between dependent MMAs on the same acc is 16.
#pragma unroll
            for (int mf = 0; mf < 4; mf++)
#pragma unroll
                for (int nf = 0; nf < 4; nf++)
                    mma16816(acc[mf][nf], ah[mf], bhf[nf]);
#pragma unroll
            for (int mf = 0; mf < 4; mf++)
#pragma unroll
                for (int nf = 0; nf < 4; nf++)
                    mma16816(acc[mf][nf], ah[mf], blf[nf]);
#pragma unroll
            for (int mf = 0; mf < 4; mf++)
#pragma unroll
                for (int nf = 0; nf < 4; nf++)
                    mma16816(acc[mf][nf], al[mf], bhf[nf]);
        }
        __syncthreads();
        if (c + 1 < C) {
            STS_AB();
            __syncthreads();
        }
    }

    // ---- fused epilogue ----
    int c0 = (lane & 3) * 2;
#pragma unroll
    for (int mf = 0; mf < 4; mf++) {
#pragma unroll
        for (int half = 0; half < 2; half++) {
            int gm = m0 + mw * 64 + mf * 16 + lg + half * 8;
            if (OP == 2) {
                size_t base = (size_t)gm * CD4;
#pragma unroll
                for (int nf = 0; nf < 4; nf++) {
#pragma unroll
                    for (int e = 0; e < 2; e++) {
                        int gn = n0 + nwp * 32 + nf * 8 + c0 + e;
                        float u = acc[mf][nf][half * 2 + e] + bias[gn];
                        g_hbuf[base + gn] =
                            0.5f * u * (1.f + erff(u * 0.7071067811865475f));
                    }
                }
            } else {
                size_t base = (size_t)gm * CD;
#pragma unroll
                for (int nf = 0; nf < 4; nf++) {
#pragma unroll
                    for (int e = 0; e < 2; e++) {
                        int gn = n0 + nwp * 32 + nf * 8 + c0 + e;
                        outf[base + gn] = g_x1[base + gn] +
                                          acc[mf][nf][half * 2 + e] + bias[gn];
                    }
                }
            }
        }
    }
#undef LDG_A
#undef LDG_B
#undef STS_AB
}

// ---------------------------------------------------------------------------
// Neighbor-list build: one block per (b,q) row; ordered compaction of adj>0.
// ---------------------------------------------------------------------------
__global__ void __launch_bounds__(256) nbr_build(const int* __restrict__ adj) {
    int bq = blockIdx.x;
    const int* row = adj + (size_t)bq * CN;
    int t = threadIdx.x, lane = t & 31, wid = t >> 5;
    int base = t * 4;
    int pr[4], c = 0;
#pragma unroll
    for (int i = 0; i < 4; i++) { pr[i] = (row[base + i] > 0); c += pr[i]; }
    // warp inclusive scan of c
    int sc = c;
#pragma unroll
    for (int o = 1; o < 32; o <<= 1) {
        int v = __shfl_up_sync(0xffffffffu, sc, o);
        if (lane >= o) sc += v;
    }
    __shared__ int wsum[8];
    if (lane == 31) wsum[wid] = sc;
    __syncthreads();
    int woff = 0;
    for (int w = 0; w < wid; w++) woff += wsum[w];
    int off = woff + sc - c;  // exclusive offset
    int* dst = g_nbr + (size_t)bq * MAXN;
#pragma unroll
    for (int i = 0; i < 4; i++) {
        if (pr[i]) {
            if (off < MAXN) dst[off] = base + i;
            off++;
        }
    }
    if (t == 255) g_ncnt[bq] = min(off, MAXN);
}

// ---------------------------------------------------------------------------
// Fused sparse attention with online softmax. One block per (b,q).
// ---------------------------------------------------------------------------
__global__ void __launch_bounds__(256) sparse_attn(
    const float* __restrict__ xin, const float* __restrict__ stoich,
    const float* __restrict__ gW, const float* __restrict__ gb) {
    int bq = blockIdx.x;
    int b = bq >> 10, q = bq & 1023;
    int t = threadIdx.x, wid = t >> 5, lane = t & 31;

    __shared__ float qrow[CD];
    __shared__ float krow[CD];
    __shared__ float sh_corr[8], sh_p[8], sh_l[8];
    __shared__ int nbr[MAXN];

    const float* nr = g_normed + (size_t)b * CN * CD;
    for (int i = t; i < CD; i += 256) qrow[i] = nr[(size_t)q * CD + i];
    int cnt = g_ncnt[bq];
    for (int i = t; i < cnt; i += 256) nbr[i] = g_nbr[(size_t)bq * MAXN + i];
    __syncthreads();

    float sq = stoich[b * CN + q];
    float m = -CUDART_INF_F, l = 0.f;
    float acc[4] = {0.f, 0.f, 0.f, 0.f};  // dims t, t+256, t+512, t+768

    for (int j = 0; j < cnt; j++) {
        int k = nbr[j];
        __syncthreads();
        for (int i = t; i < CD; i += 256) krow[i] = nr[(size_t)k * CD + i];
        __syncthreads();

        float d = 0.f;
#pragma unroll
        for (int i = 0; i < 4; i++) {
            int idx = wid * CHD + lane + 32 * i;
            d += qrow[idx] * krow[idx];
        }
#pragma unroll
        for (int o = 16; o; o >>= 1) d += __shfl_xor_sync(0xffffffffu, d, o);

        float gate = 1.f / (1.f + __expf(-(sq * gW[k] + gb[k])));
        float s = d * 0.08838834764831845f * gate;

        float mnew = fmaxf(m, s);
        float corr = __expf(m - mnew);
        float p = __expf(s - mnew);
        l = l * corr + p;
        m = mnew;
        if (lane == 0) { sh_corr[wid] = corr; sh_p[wid] = p; }
        __syncthreads();

#pragma unroll
        for (int i = 0; i < 4; i++) {
            int dpos = t + 256 * i;
            int h = dpos >> 7;
            acc[i] = acc[i] * sh_corr[h] + sh_p[h] * krow[dpos];
        }
    }

    if (lane == 0) sh_l[wid] = l;
    __syncthreads();
#pragma unroll
    for (int i = 0; i < 4; i++) {
        int dpos = t + 256 * i;
        int h = dpos >> 7;
        size_t idx = ((size_t)b * CN + q) * CD + dpos;
        g_x1[idx] = xin[idx] + acc[i] / sh_l[h];
    }
}

// ---------------------------------------------------------------------------
// LayerNorm: sel==0: x -> g_normed ; sel==1: g_x1 -> g_normed2
// ---------------------------------------------------------------------------
__global__ void ln_kernel(const float* __restrict__ xext,
                          const float* __restrict__ lng,
                          const float* __restrict__ lnb,
                          int sel) {
    int row = blockIdx.x;
    const float* src = (sel == 0 ? xext : g_x1) + (size_t)row * CD;
    float* dst = (sel == 0 ? g_normed : g_normed2) + (size_t)row * CD;
    int t = threadIdx.x;

    float v[4];
    float s = 0.f;
#pragma unroll
    for (int i = 0; i < 4; i++) { v[i] = src[t + 256 * i]; s += v[i]; }

    __shared__ float red[8];
#pragma unroll
    for (int o = 16; o; o >>= 1) s += __shfl_xor_sync(0xffffffffu, s, o);
    if ((t & 31) == 0) red[t >> 5] = s;
    __syncthreads();
    float mean = (red[0] + red[1] + red[2] + red[3] +
                  red[4] + red[5] + red[6] + red[7]) * (1.f / CD);
    __syncthreads();

    float s2 = 0.f;
#pragma unroll
    for (int i = 0; i < 4; i++) { float d = v[i] - mean; s2 += d * d; }
#pragma unroll
    for (int o = 16; o; o >>= 1) s2 += __shfl_xor_sync(0xffffffffu, s2, o);
    if ((t & 31) == 0) red[t >> 5] = s2;
    __syncthreads();
    float var = (red[0] + red[1] + red[2] + red[3] +
                 red[4] + red[5] + red[6] + red[7]) * (1.f / CD);
    float rstd = rsqrtf(var + 1e-5f);

#pragma unroll
    for (int i = 0; i < 4; i++) {
        int c = t + 256 * i;
        dst[c] = (v[i] - mean) * rstd * lng[c] + lnb[c];
    }
}

// ---------------------------------------------------------------------------
// kernel_launch
// ---------------------------------------------------------------------------
extern "C" void kernel_launch(void* const* d_in, const int* in_sizes, int n_in,
                              void* d_out, int out_size) {
    const float* x      = (const float*)d_in[0];
    const int*   adj    = (const int*)d_in[1];
    const float* stoich = (const float*)d_in[2];
    const float* ln1_g  = (const float*)d_in[3];
    const float* ln1_b  = (const float*)d_in[4];
    const float* ln2_g  = (const float*)d_in[5];
    const float* ln2_b  = (const float*)d_in[6];
    const float* W1     = (const float*)d_in[7];
    const float* b1     = (const float*)d_in[8];
    const float* W2     = (const float*)d_in[9];
    const float* b2     = (const float*)d_in[10];
    const float* gW     = (const float*)d_in[11];
    const float* gb     = (const float*)d_in[12];
    float* out = (float*)d_out;

    // LN1: x -> g_normed
    ln_kernel<<<CB * CN, 256>>>(x, ln1_g, ln1_b, 0);

    // neighbor lists from adjacency
    nbr_build<<<CB * CN, 256>>>(adj);

    // fused sparse attention (scores+gate+mask+softmax+PV+residual) -> g_x1
    sparse_attn<<<CB * CN, 256>>>(x, stoich, gW, gb);

    // LN2: g_x1 -> g_normed2
    ln_kernel<<<CB * CN, 256>>>(x, ln2_g, ln2_b, 1);

    // MLP1: gelu(normed2 @ W1 + b1) -> g_hbuf
    gemm128<2><<<dim3(32, 32), 256, DYN_SMEM>>>(b1, W1, nullptr);

    // MLP2: out = x1 + hbuf @ W2 + b2
    gemm128<3><<<dim3(8, 32), 256, DYN_SMEM>>>(b2, W2, out);
}